// round 4
// baseline (speedup 1.0000x reference)
#include <cuda_runtime.h>
#include <cuda_bf16.h>

// NBVLoss: weighted BCE reduction (HBM-bound streaming sum).
//   out = 10 * sum_{t==1} -max(log(p), -100) + 1 * sum_{t==0} -max(log(1-p), -100)
// target is exactly 0/1 -> one MUFU.LG2 per element; math fully hidden under
// the HBM stream (issue=29%). R4: revert to the R2 body (compiler-scheduled
// simple loop, regs=22) and launch exactly ONE resident wave (148 SMs x 8
// CTAs of 256 thr) of persistent grid-striders, eliminating 3 wave
// transitions + per-wave tail imbalance.

static __device__ __forceinline__ float bce_contrib(float p, float t) {
    bool is_one = (t != 0.0f);
    float x = is_one ? p : (1.0f - p);
    float l = __logf(x);              // MUFU.LG2 + FMUL(ln2)
    l = fmaxf(l, -100.0f);            // never binds (p in [1e-6, 1-1e-6])
    float w = is_one ? 10.0f : 1.0f;
    return -w * l;
}

__global__ void __launch_bounds__(256)
nbv_loss_kernel(const float4* __restrict__ pred,
                const float4* __restrict__ targ,
                float* __restrict__ out,
                int n4) {
    float acc = 0.0f;
    int stride = gridDim.x * blockDim.x;
    for (int i = blockIdx.x * blockDim.x + threadIdx.x; i < n4; i += stride) {
        float4 pv = pred[i];
        float4 tv = targ[i];
        acc += bce_contrib(pv.x, tv.x);
        acc += bce_contrib(pv.y, tv.y);
        acc += bce_contrib(pv.z, tv.z);
        acc += bce_contrib(pv.w, tv.w);
    }

    // warp reduction
    #pragma unroll
    for (int off = 16; off > 0; off >>= 1)
        acc += __shfl_xor_sync(0xFFFFFFFFu, acc, off);

    __shared__ float warp_sums[8];
    int lane = threadIdx.x & 31;
    int wid  = threadIdx.x >> 5;
    if (lane == 0) warp_sums[wid] = acc;
    __syncthreads();

    if (wid == 0) {
        float v = (lane < 8) ? warp_sums[lane] : 0.0f;
        #pragma unroll
        for (int off = 4; off > 0; off >>= 1)
            v += __shfl_xor_sync(0xFFFFFFFFu, v, off);
        if (lane == 0)
            atomicAdd(out, v);
    }
}

extern "C" void kernel_launch(void* const* d_in, const int* in_sizes, int n_in,
                              void* d_out, int out_size) {
    const float4* pred = (const float4*)d_in[0];
    const float4* targ = (const float4*)d_in[1];
    float* out = (float*)d_out;

    int n = in_sizes[0];           // 134217728, divisible by 4
    int n4 = n >> 2;               // 33554432 float4 elements

    cudaMemsetAsync(out, 0, sizeof(float));

    const int threads = 256;
    const int blocks = 148 * 8;    // exactly one resident wave (8 CTAs/SM)
    nbv_loss_kernel<<<blocks, threads>>>(pred, targ, out, n4);
}

// round 5
// speedup vs baseline: 1.0383x; 1.0383x over previous
#include <cuda_runtime.h>
#include <cuda_bf16.h>

// NBVLoss: weighted BCE reduction (HBM-bound streaming sum, ~1.07 GB read).
//   out = 10 * sum_{t==1} -max(log(p), -100) + 1 * sum_{t==0} -max(log(1-p), -100)
// target is exactly 0/1 -> one MUFU.LG2 per element; math fully hidden.
// R5: oversubscribed launch (R2 style — wave overlap smooths tails; the
// one-wave persistent grid of R4 regressed) with a power-of-two grid so the
// grid-stride loop becomes an exact counted loop (32 trips/thread, no
// data-dependent bound) -> ptxas can software-pipeline the loads.

static __device__ __forceinline__ float bce_contrib(float p, float t) {
    bool is_one = (t != 0.0f);
    float x = is_one ? p : (1.0f - p);
    float l = __logf(x);              // MUFU.LG2 + FMUL(ln2)
    l = fmaxf(l, -100.0f);            // never binds (p in [1e-6, 1-1e-6])
    float w = is_one ? 10.0f : 1.0f;
    return -w * l;
}

__global__ void __launch_bounds__(256)
nbv_loss_kernel(const float4* __restrict__ pred,
                const float4* __restrict__ targ,
                float* __restrict__ out,
                int n4) {
    const int stride = gridDim.x * blockDim.x;
    const int tid = blockIdx.x * blockDim.x + threadIdx.x;
    const int iters = n4 / stride;    // exact trip count (uniform across threads)

    float acc = 0.0f;
    int i = tid;
    for (int k = 0; k < iters; ++k, i += stride) {
        float4 pv = pred[i];
        float4 tv = targ[i];
        acc += bce_contrib(pv.x, tv.x);
        acc += bce_contrib(pv.y, tv.y);
        acc += bce_contrib(pv.z, tv.z);
        acc += bce_contrib(pv.w, tv.w);
    }
    // Remainder (empty for n4 = 2^25 with 2^20 threads)
    for (; i < n4; i += stride) {
        float4 pv = pred[i];
        float4 tv = targ[i];
        acc += bce_contrib(pv.x, tv.x);
        acc += bce_contrib(pv.y, tv.y);
        acc += bce_contrib(pv.z, tv.z);
        acc += bce_contrib(pv.w, tv.w);
    }

    // warp reduction
    #pragma unroll
    for (int off = 16; off > 0; off >>= 1)
        acc += __shfl_xor_sync(0xFFFFFFFFu, acc, off);

    __shared__ float warp_sums[8];
    int lane = threadIdx.x & 31;
    int wid  = threadIdx.x >> 5;
    if (lane == 0) warp_sums[wid] = acc;
    __syncthreads();

    if (wid == 0) {
        float v = (lane < 8) ? warp_sums[lane] : 0.0f;
        #pragma unroll
        for (int off = 4; off > 0; off >>= 1)
            v += __shfl_xor_sync(0xFFFFFFFFu, v, off);
        if (lane == 0)
            atomicAdd(out, v);
    }
}

extern "C" void kernel_launch(void* const* d_in, const int* in_sizes, int n_in,
                              void* d_out, int out_size) {
    const float4* pred = (const float4*)d_in[0];
    const float4* targ = (const float4*)d_in[1];
    float* out = (float*)d_out;

    int n = in_sizes[0];           // 134217728, divisible by 4
    int n4 = n >> 2;               // 33554432 = 2^25 float4 elements

    cudaMemsetAsync(out, 0, sizeof(float));

    const int threads = 256;
    const int blocks = 4096;       // 2^20 threads -> exactly 32 iters/thread
    nbv_loss_kernel<<<blocks, threads>>>(pred, targ, out, n4);
}

// round 6
// speedup vs baseline: 1.0527x; 1.0139x over previous
#include <cuda_runtime.h>
#include <cuda_bf16.h>

// NBVLoss: weighted BCE reduction (HBM-bound streaming sum, ~1.07 GB read).
//   out = 10 * sum_{t==1} -max(log(p), -100) + 1 * sum_{t==0} -max(log(1-p), -100)
// target is exactly 0/1 -> one MUFU.LG2 per element; math fully hidden.
// R6: keep the exact counted loop (R5 win: ptxas software-pipelines it),
// double the grid to 8192 blocks (2^21 threads, exactly 16 iters/thread)
// to shrink per-CTA duration and smooth the drain tail (occ was 71.5%).

static __device__ __forceinline__ float bce_contrib(float p, float t) {
    bool is_one = (t != 0.0f);
    float x = is_one ? p : (1.0f - p);
    float l = __logf(x);              // MUFU.LG2 + FMUL(ln2)
    l = fmaxf(l, -100.0f);            // never binds (p in [1e-6, 1-1e-6])
    float w = is_one ? 10.0f : 1.0f;
    return -w * l;
}

__global__ void __launch_bounds__(256)
nbv_loss_kernel(const float4* __restrict__ pred,
                const float4* __restrict__ targ,
                float* __restrict__ out,
                int n4) {
    const int stride = gridDim.x * blockDim.x;
    const int tid = blockIdx.x * blockDim.x + threadIdx.x;
    const int iters = n4 / stride;    // exact uniform trip count (16)

    float acc = 0.0f;
    int i = tid;
    for (int k = 0; k < iters; ++k, i += stride) {
        float4 pv = pred[i];
        float4 tv = targ[i];
        acc += bce_contrib(pv.x, tv.x);
        acc += bce_contrib(pv.y, tv.y);
        acc += bce_contrib(pv.z, tv.z);
        acc += bce_contrib(pv.w, tv.w);
    }
    // Remainder (empty for n4 = 2^25 with 2^21 threads)
    for (; i < n4; i += stride) {
        float4 pv = pred[i];
        float4 tv = targ[i];
        acc += bce_contrib(pv.x, tv.x);
        acc += bce_contrib(pv.y, tv.y);
        acc += bce_contrib(pv.z, tv.z);
        acc += bce_contrib(pv.w, tv.w);
    }

    // warp reduction
    #pragma unroll
    for (int off = 16; off > 0; off >>= 1)
        acc += __shfl_xor_sync(0xFFFFFFFFu, acc, off);

    __shared__ float warp_sums[8];
    int lane = threadIdx.x & 31;
    int wid  = threadIdx.x >> 5;
    if (lane == 0) warp_sums[wid] = acc;
    __syncthreads();

    if (wid == 0) {
        float v = (lane < 8) ? warp_sums[lane] : 0.0f;
        #pragma unroll
        for (int off = 4; off > 0; off >>= 1)
            v += __shfl_xor_sync(0xFFFFFFFFu, v, off);
        if (lane == 0)
            atomicAdd(out, v);
    }
}

extern "C" void kernel_launch(void* const* d_in, const int* in_sizes, int n_in,
                              void* d_out, int out_size) {
    const float4* pred = (const float4*)d_in[0];
    const float4* targ = (const float4*)d_in[1];
    float* out = (float*)d_out;

    int n = in_sizes[0];           // 134217728, divisible by 4
    int n4 = n >> 2;               // 33554432 = 2^25 float4 elements

    cudaMemsetAsync(out, 0, sizeof(float));

    const int threads = 256;
    const int blocks = 8192;       // 2^21 threads -> exactly 16 iters/thread
    nbv_loss_kernel<<<blocks, threads>>>(pred, targ, out, n4);
}

// round 7
// speedup vs baseline: 1.0529x; 1.0002x over previous
#include <cuda_runtime.h>
#include <cuda_bf16.h>

// NBVLoss: weighted BCE reduction (HBM-bound streaming sum, ~1.07 GB read).
//   out = 10 * sum_{t==1} -max(log(p), -100) + 1 * sum_{t==0} -max(log(1-p), -100)
// target is exactly 0/1 -> one MUFU.LG2 per element; math fully hidden.
// R7: same exact-counted-loop body (R5/R6 wins), grid doubled again to
// 16384 blocks (2^22 threads, exactly 8 iters/thread) to further shrink
// per-CTA duration and the ramp/drain tail (occ was 74%).

static __device__ __forceinline__ float bce_contrib(float p, float t) {
    bool is_one = (t != 0.0f);
    float x = is_one ? p : (1.0f - p);
    float l = __logf(x);              // MUFU.LG2 + FMUL(ln2)
    l = fmaxf(l, -100.0f);            // never binds (p in [1e-6, 1-1e-6])
    float w = is_one ? 10.0f : 1.0f;
    return -w * l;
}

__global__ void __launch_bounds__(256)
nbv_loss_kernel(const float4* __restrict__ pred,
                const float4* __restrict__ targ,
                float* __restrict__ out,
                int n4) {
    const int stride = gridDim.x * blockDim.x;
    const int tid = blockIdx.x * blockDim.x + threadIdx.x;
    const int iters = n4 / stride;    // exact uniform trip count (8)

    float acc = 0.0f;
    int i = tid;
    for (int k = 0; k < iters; ++k, i += stride) {
        float4 pv = pred[i];
        float4 tv = targ[i];
        acc += bce_contrib(pv.x, tv.x);
        acc += bce_contrib(pv.y, tv.y);
        acc += bce_contrib(pv.z, tv.z);
        acc += bce_contrib(pv.w, tv.w);
    }
    // Remainder (empty for n4 = 2^25 with 2^22 threads)
    for (; i < n4; i += stride) {
        float4 pv = pred[i];
        float4 tv = targ[i];
        acc += bce_contrib(pv.x, tv.x);
        acc += bce_contrib(pv.y, tv.y);
        acc += bce_contrib(pv.z, tv.z);
        acc += bce_contrib(pv.w, tv.w);
    }

    // warp reduction
    #pragma unroll
    for (int off = 16; off > 0; off >>= 1)
        acc += __shfl_xor_sync(0xFFFFFFFFu, acc, off);

    __shared__ float warp_sums[8];
    int lane = threadIdx.x & 31;
    int wid  = threadIdx.x >> 5;
    if (lane == 0) warp_sums[wid] = acc;
    __syncthreads();

    if (wid == 0) {
        float v = (lane < 8) ? warp_sums[lane] : 0.0f;
        #pragma unroll
        for (int off = 4; off > 0; off >>= 1)
            v += __shfl_xor_sync(0xFFFFFFFFu, v, off);
        if (lane == 0)
            atomicAdd(out, v);
    }
}

extern "C" void kernel_launch(void* const* d_in, const int* in_sizes, int n_in,
                              void* d_out, int out_size) {
    const float4* pred = (const float4*)d_in[0];
    const float4* targ = (const float4*)d_in[1];
    float* out = (float*)d_out;

    int n = in_sizes[0];           // 134217728, divisible by 4
    int n4 = n >> 2;               // 33554432 = 2^25 float4 elements

    cudaMemsetAsync(out, 0, sizeof(float));

    const int threads = 256;
    const int blocks = 16384;      // 2^22 threads -> exactly 8 iters/thread
    nbv_loss_kernel<<<blocks, threads>>>(pred, targ, out, n4);
}